// round 2
// baseline (speedup 1.0000x reference)
#include <cuda_runtime.h>
#include <math.h>

#define Bsz 16
#define NKG 1024
#define SLM 1024
#define Dd  1024
#define Hh  4096

// ---- scratch (device globals: allocation-free) ----
__device__ float g_logits[(size_t)Bsz * NKG * SLM];   // 64 MB
__device__ float g_norm[(size_t)Bsz * NKG * Dd];      // 64 MB
__device__ float g_h[(size_t)Bsz * NKG * Hh];         // 256 MB
__device__ float g_lse[Bsz * SLM];
__device__ float g_corr[Bsz * Dd];
__device__ float g_logmask[Bsz * SLM];

#define BM 128
#define BN 128
#define BK 16

// Generic tiled SGEMM: C[M,N] = A[M,K] (row-major, lda=K) * B
//   TRANSB=true : B is [N,K] row-major (NT gemm)
//   TRANSB=false: B is [K,N] row-major (NN gemm)
// Epilogues:
//   EPI 0: C = acc + V1[col]                      (logits + logmask)
//   EPI 1: C = M2[idx] + acc - V1[col]            (out1 = kg + logits@lm - corr)
//   EPI 2: C = relu(acc + V1[col])                (h = relu(x@W1 + b1))
//   EPI 3: C = acc + V1[col] + M2[idx]            (out = out1 + h@W2 + b2)
template <bool TRANSB, int EPI>
__global__ __launch_bounds__(256) void gemm_k(
    const float* __restrict__ A, const float* __restrict__ B, float* __restrict__ C,
    int M, int N, int K,
    size_t sA, size_t sB, size_t sC,
    const float* __restrict__ V1, int sV1,
    const float* __restrict__ M2, size_t sM2)
{
    __shared__ float As[BK][BM];
    __shared__ float Bs[BK][BN];

    const int b = blockIdx.z;
    A += (size_t)b * sA;
    B += (size_t)b * sB;
    C += (size_t)b * sC;
    const float* vv = V1 + (size_t)b * sV1;
    const float* m2 = (EPI == 1 || EPI == 3) ? (M2 + (size_t)b * sM2) : nullptr;

    const int tid = threadIdx.x;
    const int tx = tid & 15;
    const int ty = tid >> 4;
    const int bm = blockIdx.y * BM;
    const int bn = blockIdx.x * BN;
    const size_t ldb = TRANSB ? (size_t)K : (size_t)N;

    float acc[8][8];
#pragma unroll
    for (int i = 0; i < 8; i++)
#pragma unroll
        for (int j = 0; j < 8; j++) acc[i][j] = 0.f;

    for (int k0 = 0; k0 < K; k0 += BK) {
        // load A tile (rows K-contiguous): 512 float4 by 256 threads
#pragma unroll
        for (int i = 0; i < 2; i++) {
            int f = tid + i * 256;
            int row = f >> 2, seg = (f & 3) << 2;
            float4 v = *(const float4*)(A + (size_t)(bm + row) * K + k0 + seg);
            As[seg + 0][row] = v.x;
            As[seg + 1][row] = v.y;
            As[seg + 2][row] = v.z;
            As[seg + 3][row] = v.w;
        }
        if (TRANSB) {
#pragma unroll
            for (int i = 0; i < 2; i++) {
                int f = tid + i * 256;
                int row = f >> 2, seg = (f & 3) << 2;
                float4 v = *(const float4*)(B + (size_t)(bn + row) * ldb + k0 + seg);
                Bs[seg + 0][row] = v.x;
                Bs[seg + 1][row] = v.y;
                Bs[seg + 2][row] = v.z;
                Bs[seg + 3][row] = v.w;
            }
        } else {
#pragma unroll
            for (int i = 0; i < 2; i++) {
                int f = tid + i * 256;
                int r = f >> 5, c = (f & 31) << 2;
                *(float4*)&Bs[r][c] = *(const float4*)(B + (size_t)(k0 + r) * ldb + bn + c);
            }
        }
        __syncthreads();

#pragma unroll
        for (int kk = 0; kk < BK; kk++) {
            float a[8], bb[8];
            *(float4*)&a[0] = *(const float4*)&As[kk][ty * 4];
            *(float4*)&a[4] = *(const float4*)&As[kk][64 + ty * 4];
            *(float4*)&bb[0] = *(const float4*)&Bs[kk][tx * 4];
            *(float4*)&bb[4] = *(const float4*)&Bs[kk][64 + tx * 4];
#pragma unroll
            for (int i = 0; i < 8; i++)
#pragma unroll
                for (int j = 0; j < 8; j++) acc[i][j] += a[i] * bb[j];
        }
        __syncthreads();
    }

    // epilogue
#pragma unroll
    for (int i = 0; i < 8; i++) {
        int r = bm + ((i < 4) ? (ty * 4 + i) : (64 + ty * 4 + (i - 4)));
#pragma unroll
        for (int jh = 0; jh < 2; jh++) {
            int c0 = bn + (jh ? (64 + tx * 4) : (tx * 4));
            size_t idx = (size_t)r * N + c0;
            float t[4];
#pragma unroll
            for (int jj = 0; jj < 4; jj++) {
                float v = acc[i][jh * 4 + jj];
                int c = c0 + jj;
                if (EPI == 0) v = v + vv[c];
                if (EPI == 1) v = m2[idx + jj] + v - vv[c];
                if (EPI == 2) v = fmaxf(v + vv[c], 0.f);
                if (EPI == 3) v = v + vv[c] + m2[idx + jj];
                t[jj] = v;
            }
            float4 o = make_float4(t[0], t[1], t[2], t[3]);
            *(float4*)(C + idx) = o;
        }
    }
}

// log(mask + 1e-45) per (b,s)
__global__ __launch_bounds__(256) void logmask_k(const float* __restrict__ mask)
{
    int i = blockIdx.x * 256 + threadIdx.x;
    g_logmask[i] = logf(mask[i] + 1e-45f);
}

// column-wise (over n) logsumexp of g_logits: lse[b][s]
__global__ __launch_bounds__(256) void lse_k()
{
    int b = blockIdx.y;
    int s = blockIdx.x * 256 + threadIdx.x;
    const float* col = g_logits + (size_t)b * NKG * SLM + s;
    float m = -INFINITY, sum = 0.f;
    for (int n = 0; n < NKG; n += 8) {
        float x[8];
#pragma unroll
        for (int u = 0; u < 8; u++) x[u] = col[(size_t)(n + u) * SLM];
        float mn = x[0];
#pragma unroll
        for (int u = 1; u < 8; u++) mn = fmaxf(mn, x[u]);
        float mnew = fmaxf(m, mn);
        float p = sum * expf(m - mnew);
#pragma unroll
        for (int u = 0; u < 8; u++) p += expf(x[u] - mnew);
        sum = p;
        m = mnew;
    }
    g_lse[b * SLM + s] = m + logf(sum);
}

// corr[b][d] = sum_s lse[b][s] * lm[b][s][d]
__global__ __launch_bounds__(256) void corr_k(const float* __restrict__ lm)
{
    __shared__ float sl[SLM];
    int b = blockIdx.y;
    int tid = threadIdx.x;
    for (int i = tid; i < SLM; i += 256) sl[i] = g_lse[b * SLM + i];
    __syncthreads();
    int d = blockIdx.x * 256 + tid;
    const float* L = lm + (size_t)b * SLM * Dd + d;
    float acc = 0.f;
#pragma unroll 4
    for (int s = 0; s < SLM; s++) acc += sl[s] * L[(size_t)s * Dd];
    g_corr[b * Dd + d] = acc;
}

// row LayerNorm (D=1024), two-pass, writes g_norm
__global__ __launch_bounds__(256) void ln_k(const float* __restrict__ X,
                                            const float* __restrict__ gamma,
                                            const float* __restrict__ beta)
{
    __shared__ float red[256];
    size_t row = blockIdx.x;
    const float* x = X + row * Dd;
    int tid = threadIdx.x;
    float v[4];
#pragma unroll
    for (int i = 0; i < 4; i++) v[i] = x[i * 256 + tid];
    float s = v[0] + v[1] + v[2] + v[3];
    red[tid] = s;
    __syncthreads();
    for (int off = 128; off; off >>= 1) {
        if (tid < off) red[tid] += red[tid + off];
        __syncthreads();
    }
    float mu = red[0] * (1.0f / Dd);
    __syncthreads();
    float sq = 0.f;
#pragma unroll
    for (int i = 0; i < 4; i++) {
        float d = v[i] - mu;
        sq += d * d;
    }
    red[tid] = sq;
    __syncthreads();
    for (int off = 128; off; off >>= 1) {
        if (tid < off) red[tid] += red[tid + off];
        __syncthreads();
    }
    float var = red[0] * (1.0f / Dd);
    float rstd = rsqrtf(var + 1e-6f);
    float* y = g_norm + row * Dd;
#pragma unroll
    for (int i = 0; i < 4; i++) {
        int c = i * 256 + tid;
        y[c] = (v[i] - mu) * rstd * gamma[c] + beta[c];
    }
}

extern "C" void kernel_launch(void* const* d_in, const int* in_sizes, int n_in,
                              void* d_out, int out_size)
{
    const float* kg    = (const float*)d_in[0];
    const float* lm    = (const float*)d_in[1];
    const float* mask  = (const float*)d_in[2];
    const float* W1    = (const float*)d_in[3];
    const float* b1    = (const float*)d_in[4];
    const float* W2    = (const float*)d_in[5];
    const float* b2    = (const float*)d_in[6];
    const float* gamma = (const float*)d_in[7];
    const float* beta  = (const float*)d_in[8];
    float* out = (float*)d_out;

    // one-time symbol address resolution (deterministic; avoids repeated API
    // calls on the capture path)
    static float *logits = nullptr, *nrm = nullptr, *hbuf = nullptr,
                 *corr = nullptr, *lmask = nullptr;
    if (!logits) {
        void* p;
        cudaGetSymbolAddress(&p, g_logits);  logits = (float*)p;
        cudaGetSymbolAddress(&p, g_norm);    nrm    = (float*)p;
        cudaGetSymbolAddress(&p, g_h);       hbuf   = (float*)p;
        cudaGetSymbolAddress(&p, g_corr);    corr   = (float*)p;
        cudaGetSymbolAddress(&p, g_logmask); lmask  = (float*)p;
    }

    // 0) logmask
    logmask_k<<<(Bsz * SLM) / 256, 256>>>(mask);

    // 1) logits = kg @ lm^T + logmask       (per-batch NT gemm)
    gemm_k<true, 0><<<dim3(SLM / BN, NKG / BM, Bsz), 256>>>(
        kg, lm, logits, NKG, SLM, Dd,
        (size_t)NKG * Dd, (size_t)SLM * Dd, (size_t)NKG * SLM,
        lmask, SLM, nullptr, 0);

    // 2) column logsumexp over NKG + correction vector
    lse_k<<<dim3(SLM / 256, Bsz), 256>>>();
    corr_k<<<dim3(Dd / 256, Bsz), 256>>>(lm);

    // 3) out1 = kg + logits @ lm - corr  -> d_out   (per-batch NN gemm)
    gemm_k<false, 1><<<dim3(Dd / BN, NKG / BM, Bsz), 256>>>(
        logits, lm, out, NKG, Dd, SLM,
        (size_t)NKG * SLM, (size_t)SLM * Dd, (size_t)NKG * Dd,
        corr, Dd, kg, (size_t)NKG * Dd);

    // 4) LayerNorm(out1) -> g_norm
    ln_k<<<Bsz * NKG, 256>>>(out, gamma, beta);

    // 5) h = relu(norm @ W1 + b1)           (flattened NN gemm)
    gemm_k<false, 2><<<dim3(Hh / BN, (Bsz * NKG) / BM, 1), 256>>>(
        nrm, W1, hbuf, Bsz * NKG, Hh, Dd,
        0, 0, 0, b1, 0, nullptr, 0);

    // 6) out = out1 + h @ W2 + b2           (flattened NN gemm, in-place on d_out)
    gemm_k<false, 3><<<dim3(Dd / BN, (Bsz * NKG) / BM, 1), 256>>>(
        hbuf, W2, out, Bsz * NKG, Dd, Hh,
        0, 0, 0, b2, 0, out, 0);

    (void)in_sizes; (void)n_in; (void)out_size;
}

// round 5
// speedup vs baseline: 2.9213x; 2.9213x over previous
#include <cuda_runtime.h>
#include <cuda_bf16.h>
#include <math.h>
#include <stdint.h>

#define Bsz 16
#define NKG 1024
#define SLM 1024
#define Dd  1024
#define Hh  4096

// ---- scratch (device globals: allocation-free) ----
__device__ float g_logits[(size_t)Bsz * NKG * SLM];   // 64 MB
__device__ float g_norm[(size_t)Bsz * NKG * Dd];      // 64 MB (bf16 norm uses half)
__device__ float g_h[(size_t)Bsz * NKG * Hh];         // 256 MB (bf16 h + W1T/W2T in spare)
__device__ float g_lse[Bsz * SLM];
__device__ float g_corr[Bsz * Dd];
__device__ float g_logmask[Bsz * SLM];

__device__ __forceinline__ uint32_t smem_to_u32(const void* p) {
    uint32_t a;
    asm("{ .reg .u64 t; cvta.to.shared.u64 t, %1; cvt.u32.u64 %0, t; }"
        : "=r"(a) : "l"(p));
    return a;
}

// ======================= bf16 HMMA GEMM (FFN) =======================
// C[M,N] = A[M,K] (bf16 K-major, ldA) * B^T, B stored [N,K] bf16 K-major (ldB)
// EPI 0: outH = bf16(relu(acc + bias[col]))           (FFN1)
// EPI 1: outF += acc + bias[col]                      (FFN2, residual in outF)
//
// Tile 128x128x32, 256 threads = 8 warps (2 M x 4 N), warp tile 64x32.
// SMEM: per buffer A 128x32 bf16 (8KB) + B 128x32 bf16 (8KB); XOR swizzle
// pchunk = kchunk ^ ((row>>1)&3) on 16B chunks -> conflict-free ldmatrix.
template <int EPI>
__global__ __launch_bounds__(256) void hmma_ffn_k(
    const __nv_bfloat16* __restrict__ A, const __nv_bfloat16* __restrict__ Bw,
    int K, int ldA, int ldB,
    const float* __restrict__ bias,
    float* __restrict__ outF, __nv_bfloat16* __restrict__ outH, int ldOut)
{
    __shared__ __align__(128) char smem[2][16384];   // [buf][A 8KB | B 8KB]
    const int tid  = threadIdx.x;
    const int lane = tid & 31;
    const int wid  = tid >> 5;
    const int wm   = wid & 1;    // warp row  (64 rows)
    const int wn   = wid >> 1;   // warp col  (32 cols)
    const int bm   = blockIdx.y * 128;
    const int bn   = blockIdx.x * 128;
    const uint32_t sbase = smem_to_u32(smem);

    float acc[4][4][4];
#pragma unroll
    for (int i = 0; i < 4; i++)
#pragma unroll
        for (int j = 0; j < 4; j++)
#pragma unroll
            for (int c = 0; c < 4; c++) acc[i][j][c] = 0.f;

    // gmem prefetch regs: 2 x 16B for A, 2 x 16B for B
    uint4 ra[2], rb[2];

    auto ld_gmem = [&](const __nv_bfloat16* __restrict__ src, int ld, int row0,
                       int k0, uint4* reg) {
#pragma unroll
        for (int i = 0; i < 2; i++) {
            int id = tid + i * 256;
            int r = id >> 2, kc = id & 3;
            reg[i] = *(const uint4*)(src + (size_t)(row0 + r) * ld + k0 + kc * 8);
        }
    };
    auto st_smem = [&](const uint4* reg, char* base) {
#pragma unroll
        for (int i = 0; i < 2; i++) {
            int id = tid + i * 256;
            int r = id >> 2, kc = id & 3;
            int pc = kc ^ ((r >> 1) & 3);
            *(uint4*)(base + r * 64 + pc * 16) = reg[i];
        }
    };

    ld_gmem(A, ldA, bm, 0, ra);
    ld_gmem(Bw, ldB, bn, 0, rb);
    st_smem(ra, smem[0]);
    st_smem(rb, smem[0] + 8192);
    __syncthreads();

    const int nk = K >> 5;
    for (int kt = 0; kt < nk; kt++) {
        const int cur = kt & 1;
        if (kt + 1 < nk) {
            ld_gmem(A, ldA, bm, (kt + 1) * 32, ra);
            ld_gmem(Bw, ldB, bn, (kt + 1) * 32, rb);
        }
        const uint32_t abase = sbase + cur * 16384;
        const uint32_t bbase = abase + 8192;

#pragma unroll
        for (int ks = 0; ks < 2; ks++) {
            const int sub = lane >> 3;
            const int l7  = lane & 7;
            // A fragments: 4 M-tiles of 16x16
            uint32_t af[4][4];
#pragma unroll
            for (int mt = 0; mt < 4; mt++) {
                int r  = wm * 64 + mt * 16 + l7 + ((sub & 1) << 3);
                int kc = ks * 2 + (sub >> 1);
                uint32_t ad = abase + r * 64 + ((kc ^ ((r >> 1) & 3)) << 4);
                asm volatile(
                    "ldmatrix.sync.aligned.m8n8.x4.shared.b16 {%0,%1,%2,%3}, [%4];"
                    : "=r"(af[mt][0]), "=r"(af[mt][1]),
                      "=r"(af[mt][2]), "=r"(af[mt][3])
                    : "r"(ad));
            }
            // B fragments: 4 n8-tiles (two per ldmatrix.x4)
            uint32_t bq[4][2];
#pragma unroll
            for (int j = 0; j < 2; j++) {
                int n  = wn * 32 + (2 * j + (sub >> 1)) * 8 + l7;
                int kc = ks * 2 + (sub & 1);
                uint32_t bd = bbase + n * 64 + ((kc ^ ((n >> 1) & 3)) << 4);
                uint32_t r0, r1, r2, r3;
                asm volatile(
                    "ldmatrix.sync.aligned.m8n8.x4.shared.b16 {%0,%1,%2,%3}, [%4];"
                    : "=r"(r0), "=r"(r1), "=r"(r2), "=r"(r3)
                    : "r"(bd));
                bq[2 * j][0] = r0;     bq[2 * j][1] = r1;
                bq[2 * j + 1][0] = r2; bq[2 * j + 1][1] = r3;
            }
#pragma unroll
            for (int mt = 0; mt < 4; mt++)
#pragma unroll
                for (int nt = 0; nt < 4; nt++) {
                    asm volatile(
                        "mma.sync.aligned.m16n8k16.row.col.f32.bf16.bf16.f32 "
                        "{%0,%1,%2,%3}, {%4,%5,%6,%7}, {%8,%9}, {%0,%1,%2,%3};"
                        : "+f"(acc[mt][nt][0]), "+f"(acc[mt][nt][1]),
                          "+f"(acc[mt][nt][2]), "+f"(acc[mt][nt][3])
                        : "r"(af[mt][0]), "r"(af[mt][1]),
                          "r"(af[mt][2]), "r"(af[mt][3]),
                          "r"(bq[nt][0]), "r"(bq[nt][1]));
                }
        }
        __syncthreads();
        if (kt + 1 < nk) {
            char* nb = smem[(kt + 1) & 1];
            st_smem(ra, nb);
            st_smem(rb, nb + 8192);
            __syncthreads();
        }
    }

    // epilogue: c0,c1 -> (row = base + lane/4, cols 2*(lane%4)+{0,1}); c2,c3 -> row+8
    const int q  = lane >> 2;
    const int cc = (lane & 3) << 1;
#pragma unroll
    for (int mt = 0; mt < 4; mt++) {
        const int r0 = bm + wm * 64 + mt * 16 + q;
#pragma unroll
        for (int nt = 0; nt < 4; nt++) {
            const int col = bn + wn * 32 + nt * 8 + cc;
            const float bx = bias[col];
            const float by = bias[col + 1];
            if (EPI == 0) {
                float x0 = fmaxf(acc[mt][nt][0] + bx, 0.f);
                float x1 = fmaxf(acc[mt][nt][1] + by, 0.f);
                float x2 = fmaxf(acc[mt][nt][2] + bx, 0.f);
                float x3 = fmaxf(acc[mt][nt][3] + by, 0.f);
                *(__nv_bfloat162*)(outH + (size_t)r0 * ldOut + col) =
                    __float22bfloat162_rn(make_float2(x0, x1));
                *(__nv_bfloat162*)(outH + (size_t)(r0 + 8) * ldOut + col) =
                    __float22bfloat162_rn(make_float2(x2, x3));
            } else {
                float2* p0 = (float2*)(outF + (size_t)r0 * ldOut + col);
                float2* p1 = (float2*)(outF + (size_t)(r0 + 8) * ldOut + col);
                float2 o0 = *p0, o1 = *p1;
                o0.x += acc[mt][nt][0] + bx;
                o0.y += acc[mt][nt][1] + by;
                o1.x += acc[mt][nt][2] + bx;
                o1.y += acc[mt][nt][3] + by;
                *p0 = o0;
                *p1 = o1;
            }
        }
    }
}

// transpose fp32 [R,C] -> bf16 [C,R]
__global__ __launch_bounds__(256) void transpose_bf16_k(
    const float* __restrict__ in, __nv_bfloat16* __restrict__ out, int R, int C)
{
    __shared__ float t[32][33];
    int tx = threadIdx.x & 31, ty = threadIdx.x >> 5;  // 32x8
    int c0 = blockIdx.x * 32, r0 = blockIdx.y * 32;
#pragma unroll
    for (int i = 0; i < 4; i++)
        t[ty + 8 * i][tx] = in[(size_t)(r0 + ty + 8 * i) * C + c0 + tx];
    __syncthreads();
#pragma unroll
    for (int i = 0; i < 4; i++)
        out[(size_t)(c0 + ty + 8 * i) * R + r0 + tx] = __float2bfloat16(t[tx][ty + 8 * i]);
}

// ======================= SIMT fp32 GEMM (attention) =======================
#define BM 128
#define BN 128
#define BK 16
template <bool TRANSB, int EPI>
__global__ __launch_bounds__(256) void gemm_k(
    const float* __restrict__ A, const float* __restrict__ B, float* __restrict__ C,
    int M, int N, int K,
    size_t sA, size_t sB, size_t sC,
    const float* __restrict__ V1, int sV1,
    const float* __restrict__ M2, size_t sM2)
{
    __shared__ float As[BK][BM];
    __shared__ float Bs[BK][BN];

    const int b = blockIdx.z;
    A += (size_t)b * sA;
    B += (size_t)b * sB;
    C += (size_t)b * sC;
    const float* vv = V1 + (size_t)b * sV1;
    const float* m2 = (EPI == 1) ? (M2 + (size_t)b * sM2) : nullptr;

    const int tid = threadIdx.x;
    const int tx = tid & 15;
    const int ty = tid >> 4;
    const int bm = blockIdx.y * BM;
    const int bn = blockIdx.x * BN;
    const size_t ldb = TRANSB ? (size_t)K : (size_t)N;

    float acc[8][8];
#pragma unroll
    for (int i = 0; i < 8; i++)
#pragma unroll
        for (int j = 0; j < 8; j++) acc[i][j] = 0.f;

    for (int k0 = 0; k0 < K; k0 += BK) {
#pragma unroll
        for (int i = 0; i < 2; i++) {
            int f = tid + i * 256;
            int row = f >> 2, seg = (f & 3) << 2;
            float4 v = *(const float4*)(A + (size_t)(bm + row) * K + k0 + seg);
            As[seg + 0][row] = v.x;
            As[seg + 1][row] = v.y;
            As[seg + 2][row] = v.z;
            As[seg + 3][row] = v.w;
        }
        if (TRANSB) {
#pragma unroll
            for (int i = 0; i < 2; i++) {
                int f = tid + i * 256;
                int row = f >> 2, seg = (f & 3) << 2;
                float4 v = *(const float4*)(B + (size_t)(bn + row) * ldb + k0 + seg);
                Bs[seg + 0][row] = v.x;
                Bs[seg + 1][row] = v.y;
                Bs[seg + 2][row] = v.z;
                Bs[seg + 3][row] = v.w;
            }
        } else {
#pragma unroll
            for (int i = 0; i < 2; i++) {
                int f = tid + i * 256;
                int r = f >> 5, c = (f & 31) << 2;
                *(float4*)&Bs[r][c] = *(const float4*)(B + (size_t)(k0 + r) * ldb + bn + c);
            }
        }
        __syncthreads();

#pragma unroll
        for (int kk = 0; kk < BK; kk++) {
            float a[8], bb[8];
            *(float4*)&a[0] = *(const float4*)&As[kk][ty * 4];
            *(float4*)&a[4] = *(const float4*)&As[kk][64 + ty * 4];
            *(float4*)&bb[0] = *(const float4*)&Bs[kk][tx * 4];
            *(float4*)&bb[4] = *(const float4*)&Bs[kk][64 + tx * 4];
#pragma unroll
            for (int i = 0; i < 8; i++)
#pragma unroll
                for (int j = 0; j < 8; j++) acc[i][j] += a[i] * bb[j];
        }
        __syncthreads();
    }

#pragma unroll
    for (int i = 0; i < 8; i++) {
        int r = bm + ((i < 4) ? (ty * 4 + i) : (64 + ty * 4 + (i - 4)));
#pragma unroll
        for (int jh = 0; jh < 2; jh++) {
            int c0 = bn + (jh ? (64 + tx * 4) : (tx * 4));
            size_t idx = (size_t)r * N + c0;
            float t[4];
#pragma unroll
            for (int jj = 0; jj < 4; jj++) {
                float v = acc[i][jh * 4 + jj];
                int c = c0 + jj;
                if (EPI == 0) v = v + vv[c];
                if (EPI == 1) v = m2[idx + jj] + v - vv[c];
                t[jj] = v;
            }
            *(float4*)(C + idx) = make_float4(t[0], t[1], t[2], t[3]);
        }
    }
}

// ======================= small kernels =======================
__global__ __launch_bounds__(256) void logmask_k(const float* __restrict__ mask)
{
    int i = blockIdx.x * 256 + threadIdx.x;
    g_logmask[i] = logf(mask[i] + 1e-45f);
    g_corr[i] = 0.f;   // same size: Bsz*Dd == Bsz*SLM
}

__global__ __launch_bounds__(256) void lse_k()
{
    int b = blockIdx.y;
    int s = blockIdx.x * 256 + threadIdx.x;
    const float* col = g_logits + (size_t)b * NKG * SLM + s;
    float m = -INFINITY, sum = 0.f;
    for (int n = 0; n < NKG; n += 8) {
        float x[8];
#pragma unroll
        for (int u = 0; u < 8; u++) x[u] = col[(size_t)(n + u) * SLM];
        float mn = x[0];
#pragma unroll
        for (int u = 1; u < 8; u++) mn = fmaxf(mn, x[u]);
        float mnew = fmaxf(m, mn);
        float p = sum * expf(m - mnew);
#pragma unroll
        for (int u = 0; u < 8; u++) p += expf(x[u] - mnew);
        sum = p;
        m = mnew;
    }
    g_lse[b * SLM + s] = m + logf(sum);
}

// corr[b][d] += sum_{s in chunk} lse[b][s] * lm[b][s][d]   (4 S-chunks, atomic)
__global__ __launch_bounds__(256) void corr_k(const float* __restrict__ lm)
{
    __shared__ float sl[256];
    int b = blockIdx.y;
    int sc = blockIdx.z;
    int tid = threadIdx.x;
    sl[tid] = g_lse[b * SLM + sc * 256 + tid];
    __syncthreads();
    int d = blockIdx.x * 256 + tid;
    const float* L = lm + (size_t)b * SLM * Dd + (size_t)sc * 256 * Dd + d;
    float acc = 0.f;
#pragma unroll 4
    for (int s = 0; s < 256; s++) acc += sl[s] * L[(size_t)s * Dd];
    atomicAdd(&g_corr[b * Dd + d], acc);
}

// row LayerNorm (D=1024), writes bf16 norm
__global__ __launch_bounds__(256) void ln_k(const float* __restrict__ X,
                                            const float* __restrict__ gamma,
                                            const float* __restrict__ beta,
                                            __nv_bfloat16* __restrict__ Y)
{
    __shared__ float red[256];
    size_t row = blockIdx.x;
    const float* x = X + row * Dd;
    int tid = threadIdx.x;
    float v[4];
#pragma unroll
    for (int i = 0; i < 4; i++) v[i] = x[i * 256 + tid];
    red[tid] = v[0] + v[1] + v[2] + v[3];
    __syncthreads();
    for (int off = 128; off; off >>= 1) {
        if (tid < off) red[tid] += red[tid + off];
        __syncthreads();
    }
    float mu = red[0] * (1.0f / Dd);
    __syncthreads();
    float sq = 0.f;
#pragma unroll
    for (int i = 0; i < 4; i++) {
        float d = v[i] - mu;
        sq += d * d;
    }
    red[tid] = sq;
    __syncthreads();
    for (int off = 128; off; off >>= 1) {
        if (tid < off) red[tid] += red[tid + off];
        __syncthreads();
    }
    float rstd = rsqrtf(red[0] * (1.0f / Dd) + 1e-6f);
    __nv_bfloat16* y = Y + row * Dd;
#pragma unroll
    for (int i = 0; i < 4; i++) {
        int c = i * 256 + tid;
        y[c] = __float2bfloat16((v[i] - mu) * rstd * gamma[c] + beta[c]);
    }
}

// ======================= launch =======================
extern "C" void kernel_launch(void* const* d_in, const int* in_sizes, int n_in,
                              void* d_out, int out_size)
{
    const float* kg    = (const float*)d_in[0];
    const float* lm    = (const float*)d_in[1];
    const float* mask  = (const float*)d_in[2];
    const float* W1    = (const float*)d_in[3];
    const float* b1    = (const float*)d_in[4];
    const float* W2    = (const float*)d_in[5];
    const float* b2    = (const float*)d_in[6];
    const float* gamma = (const float*)d_in[7];
    const float* beta  = (const float*)d_in[8];
    float* out = (float*)d_out;

    static float *logits = nullptr, *nrm = nullptr, *hbuf = nullptr,
                 *corr = nullptr, *lmask = nullptr;
    if (!logits) {
        void* p;
        cudaGetSymbolAddress(&p, g_logits);  logits = (float*)p;
        cudaGetSymbolAddress(&p, g_norm);    nrm    = (float*)p;
        cudaGetSymbolAddress(&p, g_h);       hbuf   = (float*)p;
        cudaGetSymbolAddress(&p, g_corr);    corr   = (float*)p;
        cudaGetSymbolAddress(&p, g_logmask); lmask  = (float*)p;
    }

    __nv_bfloat16* normb = (__nv_bfloat16*)nrm;                       // [16384,1024]
    __nv_bfloat16* hb    = (__nv_bfloat16*)hbuf;                      // [16384,4096]
    __nv_bfloat16* W1T   = ((__nv_bfloat16*)hbuf) + (size_t)64 * 1024 * 1024;  // [4096,1024]
    __nv_bfloat16* W2T   = W1T + (size_t)4 * 1024 * 1024;                      // [1024,4096]

    const int Mtot = Bsz * NKG;  // 16384

    // 0) logmask + corr zero
    logmask_k<<<(Bsz * SLM) / 256, 256>>>(mask);

    // weight transposes (bf16, K-major for HMMA B operand)
    transpose_bf16_k<<<dim3(Hh / 32, Dd / 32), 256>>>(W1, W1T, Dd, Hh);
    transpose_bf16_k<<<dim3(Dd / 32, Hh / 32), 256>>>(W2, W2T, Hh, Dd);

    // 1) logits = kg @ lm^T + logmask       (per-batch NT, fp32 SIMT)
    gemm_k<true, 0><<<dim3(SLM / BN, NKG / BM, Bsz), 256>>>(
        kg, lm, logits, NKG, SLM, Dd,
        (size_t)NKG * Dd, (size_t)SLM * Dd, (size_t)NKG * SLM,
        lmask, SLM, nullptr, 0);

    // 2) column logsumexp + correction vector
    lse_k<<<dim3(SLM / 256, Bsz), 256>>>();
    corr_k<<<dim3(Dd / 256, Bsz, 4), 256>>>(lm);

    // 3) out1 = kg + logits @ lm - corr  -> d_out   (per-batch NN, fp32 SIMT)
    gemm_k<false, 1><<<dim3(Dd / BN, NKG / BM, Bsz), 256>>>(
        logits, lm, out, NKG, Dd, SLM,
        (size_t)NKG * SLM, (size_t)SLM * Dd, (size_t)NKG * Dd,
        corr, Dd, kg, (size_t)NKG * Dd);

    // 4) LayerNorm(out1) -> bf16 norm
    ln_k<<<Mtot, 256>>>(out, gamma, beta, normb);

    // 5) h = relu(norm @ W1 + b1) -> bf16    (HMMA)
    hmma_ffn_k<0><<<dim3(Hh / 128, Mtot / 128), 256>>>(
        normb, W1T, Dd, Dd, Dd, b1, nullptr, hb, Hh);

    // 6) out += h @ W2 + b2                  (HMMA, residual already in d_out)
    hmma_ffn_k<1><<<dim3(Dd / 128, Mtot / 128), 256>>>(
        hb, W2T, Hh, Hh, Hh, b2, out, nullptr, Dd);

    (void)in_sizes; (void)n_in; (void)out_size;
}

// round 8
// speedup vs baseline: 4.5485x; 1.5570x over previous
#include <cuda_runtime.h>
#include <cuda_bf16.h>
#include <math.h>
#include <stdint.h>

#define Bsz 16
#define NKG 1024
#define SLM 1024
#define Dd  1024
#define Hh  4096

// ---- scratch (device globals: allocation-free) ----
__device__ float g_logits[(size_t)Bsz * NKG * SLM];   // 64 MB
__device__ float g_norm[(size_t)Bsz * NKG * Dd];      // 64 MB (bf16 norm uses half)
__device__ float g_h[(size_t)Bsz * NKG * Hh];         // 256 MB (bf16 h + W1T/W2T in spare)
__device__ float g_lse[Bsz * SLM];
__device__ float g_corr[Bsz * Dd];
__device__ float g_logmask[Bsz * SLM];

__device__ __forceinline__ uint32_t smem_to_u32(const void* p) {
    uint32_t a;
    asm("{ .reg .u64 t; cvta.to.shared.u64 t, %1; cvt.u32.u64 %0, t; }"
        : "=r"(a) : "l"(p));
    return a;
}
__device__ __forceinline__ uint32_t f2tf32(float x) {
    uint32_t r;
    asm("cvt.rna.tf32.f32 %0, %1;" : "=r"(r) : "f"(x));
    return r;
}

// ======================= tf32 HMMA GEMM (attention) =======================
// C[M,N] = A[M,K] fp32 * op(B);  TRANSB: B [N,K], else B [K,N]. Per-batch (z).
// EPI 0: C = acc + vv[col]                    (logits + logmask)
// EPI 1: C = m2[idx] + acc - vv[col]          (out1 = kg + logits@lm - corr)
// Tile 128x128x16, 256 thr = 8 warps (2M x 4N), warp tile 64x32, mma m16n8k8.
// SMEM: K-major tiles at row stride 20 floats; NN B tile [16][128] stride 136.
#define TFPAD 20
#define TFPADB 136
template <bool TRANSB, int EPI>
__global__ __launch_bounds__(256) void tf32_gemm_k(
    const float* __restrict__ A, const float* __restrict__ B, float* __restrict__ C,
    int M, int N, int K,
    size_t sA, size_t sB, size_t sC,
    const float* __restrict__ V1, int sV1,
    const float* __restrict__ M2, size_t sM2)
{
    __shared__ __align__(16) uint32_t As[2][128 * TFPAD];
    __shared__ __align__(16) uint32_t Bs[2][128 * TFPAD];  // NN uses 16*136 <= this

    const int b = blockIdx.z;
    A += (size_t)b * sA;
    B += (size_t)b * sB;
    C += (size_t)b * sC;
    const float* vv = V1 + (size_t)b * sV1;
    const float* m2 = (EPI == 1) ? (M2 + (size_t)b * sM2) : nullptr;

    const int tid  = threadIdx.x;
    const int lane = tid & 31;
    const int wid  = tid >> 5;
    const int wm   = wid & 1;
    const int wn   = wid >> 1;
    const int bm   = blockIdx.y * 128;
    const int bn   = blockIdx.x * 128;

    float acc[4][4][4];
#pragma unroll
    for (int i = 0; i < 4; i++)
#pragma unroll
        for (int j = 0; j < 4; j++)
#pragma unroll
            for (int c = 0; c < 4; c++) acc[i][j][c] = 0.f;

    float4 ra[2], rb[2];

    auto ldA = [&](int k0) {
#pragma unroll
        for (int i = 0; i < 2; i++) {
            int id = tid + i * 256;
            int r = id >> 2, c = id & 3;
            ra[i] = *(const float4*)(A + (size_t)(bm + r) * K + k0 + c * 4);
        }
    };
    auto ldB = [&](int k0) {
#pragma unroll
        for (int i = 0; i < 2; i++) {
            int id = tid + i * 256;
            if (TRANSB) {
                int r = id >> 2, c = id & 3;
                rb[i] = *(const float4*)(B + (size_t)(bn + r) * K + k0 + c * 4);
            } else {
                int r = id >> 5, c = id & 31;
                rb[i] = *(const float4*)(B + (size_t)(k0 + r) * N + bn + c * 4);
            }
        }
    };
    auto stA = [&](int buf) {
#pragma unroll
        for (int i = 0; i < 2; i++) {
            int id = tid + i * 256;
            int r = id >> 2, c = id & 3;
            uint32_t* p = &As[buf][r * TFPAD + c * 4];
            p[0] = f2tf32(ra[i].x); p[1] = f2tf32(ra[i].y);
            p[2] = f2tf32(ra[i].z); p[3] = f2tf32(ra[i].w);
        }
    };
    auto stB = [&](int buf) {
#pragma unroll
        for (int i = 0; i < 2; i++) {
            int id = tid + i * 256;
            uint32_t* p;
            if (TRANSB) {
                int r = id >> 2, c = id & 3;
                p = &Bs[buf][r * TFPAD + c * 4];
            } else {
                int r = id >> 5, c = id & 31;
                p = &Bs[buf][r * TFPADB + c * 4];
            }
            p[0] = f2tf32(rb[i].x); p[1] = f2tf32(rb[i].y);
            p[2] = f2tf32(rb[i].z); p[3] = f2tf32(rb[i].w);
        }
    };

    ldA(0); ldB(0);
    stA(0); stB(0);
    __syncthreads();

    const int l4 = lane & 3, g = lane >> 2;
    const int nk = K >> 4;
    for (int kt = 0; kt < nk; kt++) {
        const int cur = kt & 1;
        if (kt + 1 < nk) { ldA((kt + 1) * 16); ldB((kt + 1) * 16); }

#pragma unroll
        for (int ks = 0; ks < 2; ks++) {
            const int kb = ks * 8 + l4;
            uint32_t af[4][4];
#pragma unroll
            for (int mt = 0; mt < 4; mt++) {
                const uint32_t* ab = &As[cur][(wm * 64 + mt * 16 + g) * TFPAD + kb];
                af[mt][0] = ab[0];
                af[mt][1] = ab[8 * TFPAD];
                af[mt][2] = ab[4];
                af[mt][3] = ab[8 * TFPAD + 4];
            }
            uint32_t bf[4][2];
#pragma unroll
            for (int nt = 0; nt < 4; nt++) {
                if (TRANSB) {
                    const uint32_t* bb = &Bs[cur][(wn * 32 + nt * 8 + g) * TFPAD + kb];
                    bf[nt][0] = bb[0];
                    bf[nt][1] = bb[4];
                } else {
                    const uint32_t* bb = &Bs[cur][kb * TFPADB + wn * 32 + nt * 8 + g];
                    bf[nt][0] = bb[0];
                    bf[nt][1] = bb[4 * TFPADB];
                }
            }
#pragma unroll
            for (int mt = 0; mt < 4; mt++)
#pragma unroll
                for (int nt = 0; nt < 4; nt++) {
                    asm volatile(
                        "mma.sync.aligned.m16n8k8.row.col.f32.tf32.tf32.f32 "
                        "{%0,%1,%2,%3}, {%4,%5,%6,%7}, {%8,%9}, {%0,%1,%2,%3};"
                        : "+f"(acc[mt][nt][0]), "+f"(acc[mt][nt][1]),
                          "+f"(acc[mt][nt][2]), "+f"(acc[mt][nt][3])
                        : "r"(af[mt][0]), "r"(af[mt][1]),
                          "r"(af[mt][2]), "r"(af[mt][3]),
                          "r"(bf[nt][0]), "r"(bf[nt][1]));
                }
        }
        __syncthreads();
        if (kt + 1 < nk) {
            stA(cur ^ 1); stB(cur ^ 1);
            __syncthreads();
        }
    }

    const int q  = lane >> 2;
    const int cc = (lane & 3) << 1;
#pragma unroll
    for (int mt = 0; mt < 4; mt++) {
        const int r0 = bm + wm * 64 + mt * 16 + q;
#pragma unroll
        for (int nt = 0; nt < 4; nt++) {
            const int col = bn + wn * 32 + nt * 8 + cc;
            const float vx = vv[col], vy = vv[col + 1];
            size_t i0 = (size_t)r0 * N + col;
            size_t i1 = (size_t)(r0 + 8) * N + col;
            float2 o0, o1;
            if (EPI == 0) {
                o0 = make_float2(acc[mt][nt][0] + vx, acc[mt][nt][1] + vy);
                o1 = make_float2(acc[mt][nt][2] + vx, acc[mt][nt][3] + vy);
            } else {
                float2 k0 = *(const float2*)(m2 + i0);
                float2 k1 = *(const float2*)(m2 + i1);
                o0 = make_float2(k0.x + acc[mt][nt][0] - vx, k0.y + acc[mt][nt][1] - vy);
                o1 = make_float2(k1.x + acc[mt][nt][2] - vx, k1.y + acc[mt][nt][3] - vy);
            }
            *(float2*)(C + i0) = o0;
            *(float2*)(C + i1) = o1;
        }
    }
}

// ======================= bf16 HMMA GEMM (FFN) =======================
template <int EPI>
__global__ __launch_bounds__(256) void hmma_ffn_k(
    const __nv_bfloat16* __restrict__ A, const __nv_bfloat16* __restrict__ Bw,
    int K, int ldA, int ldB,
    const float* __restrict__ bias,
    float* __restrict__ outF, __nv_bfloat16* __restrict__ outH, int ldOut)
{
    __shared__ __align__(128) char smem[2][16384];
    const int tid  = threadIdx.x;
    const int lane = tid & 31;
    const int wid  = tid >> 5;
    const int wm   = wid & 1;
    const int wn   = wid >> 1;
    const int bm   = blockIdx.y * 128;
    const int bn   = blockIdx.x * 128;
    const uint32_t sbase = smem_to_u32(smem);

    float acc[4][4][4];
#pragma unroll
    for (int i = 0; i < 4; i++)
#pragma unroll
        for (int j = 0; j < 4; j++)
#pragma unroll
            for (int c = 0; c < 4; c++) acc[i][j][c] = 0.f;

    uint4 ra[2], rb[2];
    auto ld_gmem = [&](const __nv_bfloat16* __restrict__ src, int ld, int row0,
                       int k0, uint4* reg) {
#pragma unroll
        for (int i = 0; i < 2; i++) {
            int id = tid + i * 256;
            int r = id >> 2, kc = id & 3;
            reg[i] = *(const uint4*)(src + (size_t)(row0 + r) * ld + k0 + kc * 8);
        }
    };
    auto st_smem = [&](const uint4* reg, char* base) {
#pragma unroll
        for (int i = 0; i < 2; i++) {
            int id = tid + i * 256;
            int r = id >> 2, kc = id & 3;
            int pc = kc ^ ((r >> 1) & 3);
            *(uint4*)(base + r * 64 + pc * 16) = reg[i];
        }
    };

    ld_gmem(A, ldA, bm, 0, ra);
    ld_gmem(Bw, ldB, bn, 0, rb);
    st_smem(ra, smem[0]);
    st_smem(rb, smem[0] + 8192);
    __syncthreads();

    const int nk = K >> 5;
    for (int kt = 0; kt < nk; kt++) {
        const int cur = kt & 1;
        if (kt + 1 < nk) {
            ld_gmem(A, ldA, bm, (kt + 1) * 32, ra);
            ld_gmem(Bw, ldB, bn, (kt + 1) * 32, rb);
        }
        const uint32_t abase = sbase + cur * 16384;
        const uint32_t bbase = abase + 8192;

#pragma unroll
        for (int ks = 0; ks < 2; ks++) {
            const int sub = lane >> 3;
            const int l7  = lane & 7;
            uint32_t af[4][4];
#pragma unroll
            for (int mt = 0; mt < 4; mt++) {
                int r  = wm * 64 + mt * 16 + l7 + ((sub & 1) << 3);
                int kc = ks * 2 + (sub >> 1);
                uint32_t ad = abase + r * 64 + ((kc ^ ((r >> 1) & 3)) << 4);
                asm volatile(
                    "ldmatrix.sync.aligned.m8n8.x4.shared.b16 {%0,%1,%2,%3}, [%4];"
                    : "=r"(af[mt][0]), "=r"(af[mt][1]),
                      "=r"(af[mt][2]), "=r"(af[mt][3])
                    : "r"(ad));
            }
            uint32_t bq[4][2];
#pragma unroll
            for (int j = 0; j < 2; j++) {
                int n  = wn * 32 + (2 * j + (sub >> 1)) * 8 + l7;
                int kc = ks * 2 + (sub & 1);
                uint32_t bd = bbase + n * 64 + ((kc ^ ((n >> 1) & 3)) << 4);
                uint32_t r0, r1, r2, r3;
                asm volatile(
                    "ldmatrix.sync.aligned.m8n8.x4.shared.b16 {%0,%1,%2,%3}, [%4];"
                    : "=r"(r0), "=r"(r1), "=r"(r2), "=r"(r3)
                    : "r"(bd));
                bq[2 * j][0] = r0;     bq[2 * j][1] = r1;
                bq[2 * j + 1][0] = r2; bq[2 * j + 1][1] = r3;
            }
#pragma unroll
            for (int mt = 0; mt < 4; mt++)
#pragma unroll
                for (int nt = 0; nt < 4; nt++) {
                    asm volatile(
                        "mma.sync.aligned.m16n8k16.row.col.f32.bf16.bf16.f32 "
                        "{%0,%1,%2,%3}, {%4,%5,%6,%7}, {%8,%9}, {%0,%1,%2,%3};"
                        : "+f"(acc[mt][nt][0]), "+f"(acc[mt][nt][1]),
                          "+f"(acc[mt][nt][2]), "+f"(acc[mt][nt][3])
                        : "r"(af[mt][0]), "r"(af[mt][1]),
                          "r"(af[mt][2]), "r"(af[mt][3]),
                          "r"(bq[nt][0]), "r"(bq[nt][1]));
                }
        }
        __syncthreads();
        if (kt + 1 < nk) {
            char* nb = smem[(kt + 1) & 1];
            st_smem(ra, nb);
            st_smem(rb, nb + 8192);
            __syncthreads();
        }
    }

    const int q  = lane >> 2;
    const int cc = (lane & 3) << 1;
#pragma unroll
    for (int mt = 0; mt < 4; mt++) {
        const int r0 = bm + wm * 64 + mt * 16 + q;
#pragma unroll
        for (int nt = 0; nt < 4; nt++) {
            const int col = bn + wn * 32 + nt * 8 + cc;
            const float bx = bias[col];
            const float by = bias[col + 1];
            if (EPI == 0) {
                float x0 = fmaxf(acc[mt][nt][0] + bx, 0.f);
                float x1 = fmaxf(acc[mt][nt][1] + by, 0.f);
                float x2 = fmaxf(acc[mt][nt][2] + bx, 0.f);
                float x3 = fmaxf(acc[mt][nt][3] + by, 0.f);
                *(__nv_bfloat162*)(outH + (size_t)r0 * ldOut + col) =
                    __float22bfloat162_rn(make_float2(x0, x1));
                *(__nv_bfloat162*)(outH + (size_t)(r0 + 8) * ldOut + col) =
                    __float22bfloat162_rn(make_float2(x2, x3));
            } else {
                float2* p0 = (float2*)(outF + (size_t)r0 * ldOut + col);
                float2* p1 = (float2*)(outF + (size_t)(r0 + 8) * ldOut + col);
                float2 o0 = *p0, o1 = *p1;
                o0.x += acc[mt][nt][0] + bx;
                o0.y += acc[mt][nt][1] + by;
                o1.x += acc[mt][nt][2] + bx;
                o1.y += acc[mt][nt][3] + by;
                *p0 = o0;
                *p1 = o1;
            }
        }
    }
}

// transpose fp32 [R,C] -> bf16 [C,R]
__global__ __launch_bounds__(256) void transpose_bf16_k(
    const float* __restrict__ in, __nv_bfloat16* __restrict__ out, int R, int C)
{
    __shared__ float t[32][33];
    int tx = threadIdx.x & 31, ty = threadIdx.x >> 5;
    int c0 = blockIdx.x * 32, r0 = blockIdx.y * 32;
#pragma unroll
    for (int i = 0; i < 4; i++)
        t[ty + 8 * i][tx] = in[(size_t)(r0 + ty + 8 * i) * C + c0 + tx];
    __syncthreads();
#pragma unroll
    for (int i = 0; i < 4; i++)
        out[(size_t)(c0 + ty + 8 * i) * R + r0 + tx] = __float2bfloat16(t[tx][ty + 8 * i]);
}

// ======================= small kernels =======================
__global__ __launch_bounds__(256) void logmask_k(const float* __restrict__ mask)
{
    int i = blockIdx.x * 256 + threadIdx.x;
    g_logmask[i] = logf(mask[i] + 1e-45f);
    g_corr[i] = 0.f;
}

__global__ __launch_bounds__(256) void lse_k()
{
    int b = blockIdx.y;
    int s = blockIdx.x * 256 + threadIdx.x;
    const float* col = g_logits + (size_t)b * NKG * SLM + s;
    float m = -INFINITY, sum = 0.f;
    for (int n = 0; n < NKG; n += 8) {
        float x[8];
#pragma unroll
        for (int u = 0; u < 8; u++) x[u] = col[(size_t)(n + u) * SLM];
        float mn = x[0];
#pragma unroll
        for (int u = 1; u < 8; u++) mn = fmaxf(mn, x[u]);
        float mnew = fmaxf(m, mn);
        float p = sum * expf(m - mnew);
#pragma unroll
        for (int u = 0; u < 8; u++) p += expf(x[u] - mnew);
        sum = p;
        m = mnew;
    }
    g_lse[b * SLM + s] = m + logf(sum);
}

__global__ __launch_bounds__(256) void corr_k(const float* __restrict__ lm)
{
    __shared__ float sl[256];
    int b = blockIdx.y;
    int sc = blockIdx.z;
    int tid = threadIdx.x;
    sl[tid] = g_lse[b * SLM + sc * 256 + tid];
    __syncthreads();
    int d = blockIdx.x * 256 + tid;
    const float* L = lm + (size_t)b * SLM * Dd + (size_t)sc * 256 * Dd + d;
    float acc = 0.f;
#pragma unroll 4
    for (int s = 0; s < 256; s++) acc += sl[s] * L[(size_t)s * Dd];
    atomicAdd(&g_corr[b * Dd + d], acc);
}

__global__ __launch_bounds__(256) void ln_k(const float* __restrict__ X,
                                            const float* __restrict__ gamma,
                                            const float* __restrict__ beta,
                                            __nv_bfloat16* __restrict__ Y)
{
    __shared__ float red[256];
    size_t row = blockIdx.x;
    const float* x = X + row * Dd;
    int tid = threadIdx.x;
    float v[4];
#pragma unroll
    for (int i = 0; i < 4; i++) v[i] = x[i * 256 + tid];
    red[tid] = v[0] + v[1] + v[2] + v[3];
    __syncthreads();
    for (int off = 128; off; off >>= 1) {
        if (tid < off) red[tid] += red[tid + off];
        __syncthreads();
    }
    float mu = red[0] * (1.0f / Dd);
    __syncthreads();
    float sq = 0.f;
#pragma unroll
    for (int i = 0; i < 4; i++) {
        float d = v[i] - mu;
        sq += d * d;
    }
    red[tid] = sq;
    __syncthreads();
    for (int off = 128; off; off >>= 1) {
        if (tid < off) red[tid] += red[tid + off];
        __syncthreads();
    }
    float rstd = rsqrtf(red[0] * (1.0f / Dd) + 1e-6f);
    __nv_bfloat16* y = Y + row * Dd;
#pragma unroll
    for (int i = 0; i < 4; i++) {
        int c = i * 256 + tid;
        y[c] = __float2bfloat16((v[i] - mu) * rstd * gamma[c] + beta[c]);
    }
}

// ======================= launch =======================
extern "C" void kernel_launch(void* const* d_in, const int* in_sizes, int n_in,
                              void* d_out, int out_size)
{
    const float* kg    = (const float*)d_in[0];
    const float* lm    = (const float*)d_in[1];
    const float* mask  = (const float*)d_in[2];
    const float* W1    = (const float*)d_in[3];
    const float* b1    = (const float*)d_in[4];
    const float* W2    = (const float*)d_in[5];
    const float* b2    = (const float*)d_in[6];
    const float* gamma = (const float*)d_in[7];
    const float* beta  = (const float*)d_in[8];
    float* out = (float*)d_out;

    static float *logits = nullptr, *nrm = nullptr, *hbuf = nullptr,
                 *corr = nullptr, *lmask = nullptr;
    if (!logits) {
        void* p;
        cudaGetSymbolAddress(&p, g_logits);  logits = (float*)p;
        cudaGetSymbolAddress(&p, g_norm);    nrm    = (float*)p;
        cudaGetSymbolAddress(&p, g_h);       hbuf   = (float*)p;
        cudaGetSymbolAddress(&p, g_corr);    corr   = (float*)p;
        cudaGetSymbolAddress(&p, g_logmask); lmask  = (float*)p;
    }

    __nv_bfloat16* normb = (__nv_bfloat16*)nrm;                       // [16384,1024]
    __nv_bfloat16* hb    = (__nv_bfloat16*)hbuf;                      // [16384,4096]
    __nv_bfloat16* W1T   = ((__nv_bfloat16*)hbuf) + (size_t)64 * 1024 * 1024;  // [4096,1024]
    __nv_bfloat16* W2T   = W1T + (size_t)4 * 1024 * 1024;                      // [1024,4096]

    const int Mtot = Bsz * NKG;  // 16384

    // 0) logmask + corr zero
    logmask_k<<<(Bsz * SLM) / 256, 256>>>(mask);

    // weight transposes (bf16, K-major for HMMA B operand)
    transpose_bf16_k<<<dim3(Hh / 32, Dd / 32), 256>>>(W1, W1T, Dd, Hh);
    transpose_bf16_k<<<dim3(Dd / 32, Hh / 32), 256>>>(W2, W2T, Hh, Dd);

    // 1) logits = kg @ lm^T + logmask       (per-batch NT, tf32 HMMA)
    tf32_gemm_k<true, 0><<<dim3(SLM / 128, NKG / 128, Bsz), 256>>>(
        kg, lm, logits, NKG, SLM, Dd,
        (size_t)NKG * Dd, (size_t)SLM * Dd, (size_t)NKG * SLM,
        lmask, SLM, nullptr, 0);

    // 2) column logsumexp + correction vector
    lse_k<<<dim3(SLM / 256, Bsz), 256>>>();
    corr_k<<<dim3(Dd / 256, Bsz, 4), 256>>>(lm);

    // 3) out1 = kg + logits @ lm - corr  -> d_out   (per-batch NN, tf32 HMMA)
    tf32_gemm_k<false, 1><<<dim3(Dd / 128, NKG / 128, Bsz), 256>>>(
        logits, lm, out, NKG, Dd, SLM,
        (size_t)NKG * SLM, (size_t)SLM * Dd, (size_t)NKG * Dd,
        corr, Dd, kg, (size_t)NKG * Dd);

    // 4) LayerNorm(out1) -> bf16 norm
    ln_k<<<Mtot, 256>>>(out, gamma, beta, normb);

    // 5) h = relu(norm @ W1 + b1) -> bf16    (HMMA)
    hmma_ffn_k<0><<<dim3(Hh / 128, Mtot / 128), 256>>>(
        normb, W1T, Dd, Dd, Dd, b1, nullptr, hb, Hh);

    // 6) out += h @ W2 + b2                  (HMMA, residual already in d_out)
    hmma_ffn_k<1><<<dim3(Dd / 128, Mtot / 128), 256>>>(
        hb, W2T, Hh, Hh, Hh, b2, out, nullptr, Dd);

    (void)in_sizes; (void)n_in; (void)out_size;
}